// round 16
// baseline (speedup 1.0000x reference)
#include <cuda_runtime.h>
#include <math.h>

#define CDIV(a,b) (((a)+(b)-1)/(b))
#define NS0 (4*64*64*64)
#define NS1 (4*32*32*32)
#define NS2 (4*16*16*16)
#define NS3 (4*8*8*8)
#define GBN 128

__device__ __align__(16) float g_mem[2*16*NS0];
#define BUF_A 0L
#define BUF_B ((long)4*NS0)

#define IA0 0
#define IA1 (IA0+NS0)
#define IA2 (IA1+NS1)
#define IA3 (IA2+NS2)
#define IB0 (IA3+NS3)
#define IB1 (IB0+NS0)
#define IB2 (IB1+NS1)
#define LA0 (IB2+NS2)
#define LA1 (LA0+NS0)
#define LA2 (LA1+NS1)
#define LA3 (LA2+NS2)
#define LB0 (LA3+NS3)
#define LB1 (LB0+NS0)
#define LB2 (LB1+NS1)
#define I2B0 (LB2+NS2)
#define I2B1 (I2B0+NS0)
#define I2B2 (I2B1+NS1)
#define ITOT (I2B2+NS2)
__device__ int g_int[ITOT];

#define CA0 0
#define CA1 1
#define CA2 2
#define CA3 3
#define CB2 4
#define CB1 5
#define CB0 6
__device__ int    g_cnt[8];
__device__ volatile unsigned g_desc[7*4096];
__device__ double g_psum[16*GBN];
__device__ double g_psq [16*GBN];
__device__ float  g_A[16];
__device__ float  g_Bb[16];
__device__ int    g_ticket;

typedef unsigned long long ull;

__device__ __forceinline__ ull pack2(float v) {
    ull r; asm("mov.b64 %0, {%1, %1};" : "=l"(r) : "f"(v)); return r;
}
__device__ __forceinline__ void fma2(ull& a, ull v, ull w) {
    asm("fma.rn.f32x2 %0, %1, %2, %0;" : "+l"(a) : "l"(v), "l"(w));
}
__device__ __forceinline__ float2 unpack2(ull a) {
    float2 f; asm("mov.b64 {%0, %1}, %2;" : "=f"(f.x), "=f"(f.y) : "l"(a)); return f;
}

#define LOADP(dst, f4, r) do { float4 _v; \
    _v=(f4)[(r)];          dst[0]=_v.x; dst[1]=_v.y; dst[2]=_v.z; dst[3]=_v.w; \
    _v=(f4)[NS0+(r)];      dst[4]=_v.x; dst[5]=_v.y; dst[6]=_v.z; dst[7]=_v.w; \
    _v=(f4)[2*NS0+(r)];    dst[8]=_v.x; dst[9]=_v.y; dst[10]=_v.z; dst[11]=_v.w; \
    _v=(f4)[3*NS0+(r)];    dst[12]=_v.x; dst[13]=_v.y; dst[14]=_v.z; dst[15]=_v.w; } while(0)

#define STOREP(f4, r, a) do { float2 _f; float4 _q; \
    _f=unpack2(a[0]); _q.x=_f.x; _q.y=_f.y; _f=unpack2(a[1]); _q.z=_f.x; _q.w=_f.y; (f4)[(r)]=_q; \
    _f=unpack2(a[2]); _q.x=_f.x; _q.y=_f.y; _f=unpack2(a[3]); _q.z=_f.x; _q.w=_f.y; (f4)[NS0+(r)]=_q; \
    _f=unpack2(a[4]); _q.x=_f.x; _q.y=_f.y; _f=unpack2(a[5]); _q.z=_f.x; _q.w=_f.y; (f4)[2*NS0+(r)]=_q; \
    _f=unpack2(a[6]); _q.x=_f.x; _q.y=_f.y; _f=unpack2(a[7]); _q.z=_f.x; _q.w=_f.y; (f4)[3*NS0+(r)]=_q; } while(0)

#define FMA16(acc, q, wr) do { \
    _Pragma("unroll") \
    for (int _ci = 0; _ci < 16; _ci++) { \
        ull _v = pack2(q[_ci]); \
        const ulonglong2* _wp = (const ulonglong2*)((wr) + _ci*16); \
        _Pragma("unroll") \
        for (int _h = 0; _h < 4; _h++) { \
            ulonglong2 _wv = _wp[_h]; \
            fma2(acc[2*_h+0], _v, _wv.x); \
            fma2(acc[2*_h+1], _v, _wv.y); \
        } \
    } } while(0)

// --------------------------- input -----------------------------------------

__global__ void k_init(int n4) {
    float4* p = (float4*)g_mem;
    float4 z = make_float4(0.f,0.f,0.f,0.f);
    for (int i = blockIdx.x*blockDim.x + threadIdx.x; i < n4; i += gridDim.x*blockDim.x)
        p[i] = z;
    for (int i = blockIdx.x*blockDim.x + threadIdx.x; i < 7*4096; i += gridDim.x*blockDim.x)
        g_desc[i] = 0u;
    if (blockIdx.x == 0 && threadIdx.x == 0) g_ticket = 0;
}

__global__ void k_scatter(const float* __restrict__ data, const int* __restrict__ cid, int n) {
    int i = blockIdx.x*blockDim.x + threadIdx.x;
    if (i >= n) return;
    int z = (int)data[i*5+0];
    int y = (int)data[i*5+1];
    int x = (int)data[i*5+2];
    int b = cid[i];
    atomicAdd(&g_mem[((((long)b*64 + z)*64 + y)*64 + x)], 1.0f);
}

// ----- single-pass compaction: publish aggregate, parallel spin-prefix -----

__device__ __forceinline__ bool is_active(int mode, int i, int lg, long foff, int ioff) {
    if (mode == 0) return g_mem[foff + i] > 0.f;
    if (mode == 1) {
        int S = 1 << lg;
        int b = i >> (3*lg), r = i & ((1<<(3*lg))-1);
        int z = r >> (2*lg), y = (r >> lg) & (S-1), x = r & (S-1);
        int flg = lg + 1;
        #pragma unroll
        for (int a = 0; a < 2; a++)
        #pragma unroll
        for (int bb = 0; bb < 2; bb++)
        #pragma unroll
        for (int c = 0; c < 2; c++) {
            int nb = (b << (3*flg)) + ((2*z+a) << (2*flg)) + ((2*y+bb) << flg) + (2*x+c);
            if (g_int[ioff + nb] >= 0) return true;
        }
        return false;
    }
    int r = g_int[ioff + i];
    if (r < 0) return false;
    return ((const float4*)g_mem + foff)[r].x > 0.f;
}

__global__ void k_emit1(int inv, int mode, int lg, long foff, int ioff,
                        int idxout, int idxout2, int listout, int cidx) {
    int t = threadIdx.x, b = blockIdx.x;
    int i = b*256 + t;
    bool a = is_active(mode, i, lg, foff, ioff);
    unsigned bal = __ballot_sync(0xffffffffu, a);
    __shared__ int ws[8];
    __shared__ int sh[8];
    __shared__ int sbase;
    int lane = t & 31, wid = t >> 5;
    if (lane == 0) ws[wid] = __popc(bal);
    __syncthreads();
    int agg = 0;
    #pragma unroll
    for (int j = 0; j < 8; j++) agg += ws[j];
    volatile unsigned* d = g_desc + inv*4096;
    if (t == 0) d[b] = 0x80000000u | (unsigned)agg;
    int pre = 0;
    for (int j = t; j < b; j += 256) {
        unsigned v;
        do { v = d[j]; } while (!(v & 0x80000000u));
        pre += (int)(v & 0x7FFFFFFFu);
    }
    #pragma unroll
    for (int o = 16; o > 0; o >>= 1) pre += __shfl_down_sync(0xffffffffu, pre, o);
    if (lane == 0) sh[wid] = pre;
    __syncthreads();
    if (t == 0) {
        int s = 0;
        #pragma unroll
        for (int j = 0; j < 8; j++) s += sh[j];
        sbase = s;
        if (b == gridDim.x - 1) g_cnt[cidx] = s + agg;
    }
    __syncthreads();
    int base = sbase;
    int woff = 0;
    #pragma unroll
    for (int j = 0; j < 8; j++) if (j < wid) woff += ws[j];
    int pos = base + woff + __popc(bal & ((1u << lane) - 1u));
    g_int[idxout + i] = a ? pos : -1;
    if (idxout2 >= 0)
        g_int[idxout2 + i] = a ? g_int[ioff + i] : -1;
    if (a) g_int[listout + pos] = i;
}

// ------------------------------- BatchNorm ---------------------------------

__global__ void k_bnstats(long in4, int cidx, const float* __restrict__ gamma,
                          const float* __restrict__ beta) {
    int cnt = g_cnt[cidx];
    const float4* f = (const float4*)g_mem + in4;
    float s[16], q[16];
    #pragma unroll
    for (int c = 0; c < 16; c++) { s[c] = 0.f; q[c] = 0.f; }
    for (int i = blockIdx.x*256 + threadIdx.x; i < cnt; i += GBN*256) {
        #pragma unroll
        for (int h = 0; h < 4; h++) {
            float4 v = f[h*NS0 + i];
            s[4*h+0] += v.x; q[4*h+0] += v.x*v.x;
            s[4*h+1] += v.y; q[4*h+1] += v.y*v.y;
            s[4*h+2] += v.z; q[4*h+2] += v.z*v.z;
            s[4*h+3] += v.w; q[4*h+3] += v.w*v.w;
        }
    }
    int lane = threadIdx.x & 31, wid = threadIdx.x >> 5;
    __shared__ float shs[8][16], shq[8][16];
    #pragma unroll
    for (int c = 0; c < 16; c++) {
        float a = s[c], b = q[c];
        #pragma unroll
        for (int o = 16; o > 0; o >>= 1) {
            a += __shfl_down_sync(0xffffffffu, a, o);
            b += __shfl_down_sync(0xffffffffu, b, o);
        }
        if (lane == 0) { shs[wid][c] = a; shq[wid][c] = b; }
    }
    __syncthreads();
    if (threadIdx.x < 16) {
        double A = 0.0, Bq = 0.0;
        #pragma unroll
        for (int j = 0; j < 8; j++) { A += (double)shs[j][threadIdx.x]; Bq += (double)shq[j][threadIdx.x]; }
        g_psum[threadIdx.x*GBN + blockIdx.x] = A;
        g_psq [threadIdx.x*GBN + blockIdx.x] = Bq;
    }
    __threadfence();
    __shared__ int lastf;
    if (threadIdx.x == 0) {
        int o = atomicAdd(&g_ticket, 1);
        lastf = (o == GBN - 1) ? 1 : 0;
    }
    __syncthreads();
    if (lastf) {
        __threadfence();
        if (threadIdx.x < 16) {
            int c = threadIdx.x;
            volatile double* vs = g_psum;
            volatile double* vq = g_psq;
            double S = 0.0, Q = 0.0;
            for (int g = 0; g < GBN; g++) { S += vs[c*GBN + g]; Q += vq[c*GBN + g]; }
            double n = (double)cnt; if (n < 1.0) n = 1.0;
            double mean = S / n;
            double var  = Q / n - mean*mean;
            double inv  = 1.0 / sqrt(var + 1e-4);
            double Af   = (double)gamma[c] * inv;
            g_A[c]  = (float)Af;
            g_Bb[c] = (float)((double)beta[c] - mean*Af);
        }
        if (threadIdx.x == 0) g_ticket = 0;
    }
}

__global__ void k_bnapply(long in4, int cidx) {
    int cnt = g_cnt[cidx];
    int i = blockIdx.x*256 + threadIdx.x;
    if (i >= cnt) return;
    float4* f = (float4*)g_mem + in4;
    #pragma unroll
    for (int h = 0; h < 4; h++) {
        float4 v = f[h*NS0 + i];
        v.x = fmaf(v.x, g_A[4*h+0], g_Bb[4*h+0]); v.x = v.x > 0.f ? v.x : 0.f;
        v.y = fmaf(v.y, g_A[4*h+1], g_Bb[4*h+1]); v.y = v.y > 0.f ? v.y : 0.f;
        v.z = fmaf(v.z, g_A[4*h+2], g_Bb[4*h+2]); v.z = v.z > 0.f ? v.z : 0.f;
        v.w = fmaf(v.w, g_A[4*h+3], g_Bb[4*h+3]); v.w = v.w > 0.f ? v.w : 0.f;
        f[h*NS0 + i] = v;
    }
}

// ------------------------------ convolutions -------------------------------

__global__ void k_prep(long out4, const float* __restrict__ w) {
    int cnt = g_cnt[CA0];
    if (blockIdx.x*256 >= cnt) return;
    __shared__ __align__(16) float sw[432];
    for (int i = threadIdx.x; i < 432; i += 256) sw[i] = w[i];
    __syncthreads();
    int i = blockIdx.x*256 + threadIdx.x;
    if (i >= cnt) return;
    int site = g_int[LA0 + i];
    const int lg = 6, S = 64;
    int b = site >> 18, r = site & 0x3ffff;
    int z = r >> 12, y = (r >> 6) & 63, x = r & 63;
    ull a[8];
    #pragma unroll
    for (int p = 0; p < 8; p++) a[p] = 0ull;
    #pragma unroll 1
    for (int dz = 0; dz < 3; dz++) {
        int zz = z + dz - 1; if ((unsigned)zz >= (unsigned)S) continue;
        #pragma unroll 1
        for (int dy = 0; dy < 3; dy++) {
            int yy = y + dy - 1; if ((unsigned)yy >= (unsigned)S) continue;
            #pragma unroll
            for (int dx = 0; dx < 3; dx++) {
                int xx = x + dx - 1; if ((unsigned)xx >= (unsigned)S) continue;
                float v = g_mem[(b << (3*lg)) + (zz << (2*lg)) + (yy << lg) + xx];
                if (v == 0.f) continue;
                ull vv = pack2(v);
                const ulonglong2* wp = (const ulonglong2*)(sw + ((dz*3+dy)*3+dx)*16);
                #pragma unroll
                for (int h = 0; h < 4; h++) {
                    ulonglong2 wv = wp[h];
                    fma2(a[2*h+0], vv, wv.x);
                    fma2(a[2*h+1], vv, wv.y);
                }
            }
        }
    }
    float4* fo = (float4*)g_mem + out4;
    STOREP(fo, i, a);
}

// submanifold k=3: 2 sites/thread, batched rank prefetch, per-tap skip
__global__ void __launch_bounds__(128) k_conv3(long in4, long out4,
        const float* __restrict__ w, int ioff, int loff, int cidx, int lg) {
    int cnt = g_cnt[cidx];
    if (blockIdx.x*256 >= cnt) return;
    __shared__ __align__(16) float sw[6912];
    {
        const float4* ws = (const float4*)w;
        float4* wd = (float4*)sw;
        for (int i = threadIdx.x; i < 1728; i += 128) wd[i] = ws[i];
    }
    __syncthreads();
    int t = blockIdx.x*128 + threadIdx.x;
    int i0 = 2*t, i1 = i0 + 1;
    if (i0 >= cnt) return;
    bool has1 = i1 < cnt;
    int S = 1 << lg, M = (1 << (3*lg)) - 1;
    int site0 = g_int[loff + i0];
    int site1 = has1 ? g_int[loff + i1] : site0;
    int b0 = site0 >> (3*lg), r0 = site0 & M;
    int z0 = r0 >> (2*lg), y0 = (r0 >> lg) & (S-1), x0 = r0 & (S-1);
    int b1 = site1 >> (3*lg), r1 = site1 & M;
    int z1 = r1 >> (2*lg), y1 = (r1 >> lg) & (S-1), x1 = r1 & (S-1);
    const float4* fin = (const float4*)g_mem + in4;
    ull a0[8], a1[8];
    #pragma unroll
    for (int p = 0; p < 8; p++) { a0[p] = 0ull; a1[p] = 0ull; }
    #pragma unroll 1
    for (int dz = 0; dz < 3; dz++) {
        int zz0 = z0 + dz - 1, zz1 = z1 + dz - 1;
        bool zk0 = (unsigned)zz0 < (unsigned)S;
        bool zk1 = has1 && ((unsigned)zz1 < (unsigned)S);
        int rr0[9], rr1[9];
        #pragma unroll
        for (int dy = 0; dy < 3; dy++)
        #pragma unroll
        for (int dx = 0; dx < 3; dx++) {
            int k = dy*3 + dx;
            int yy0 = y0+dy-1, xx0 = x0+dx-1;
            rr0[k] = -1;
            if (zk0 && (unsigned)yy0 < (unsigned)S && (unsigned)xx0 < (unsigned)S)
                rr0[k] = g_int[ioff + ((b0 << (3*lg)) + (zz0 << (2*lg)) + (yy0 << lg) + xx0)];
            int yy1 = y1+dy-1, xx1 = x1+dx-1;
            rr1[k] = -1;
            if (zk1 && (unsigned)yy1 < (unsigned)S && (unsigned)xx1 < (unsigned)S)
                rr1[k] = g_int[ioff + ((b1 << (3*lg)) + (zz1 << (2*lg)) + (yy1 << lg) + xx1)];
        }
        #pragma unroll
        for (int k = 0; k < 9; k++) {
            if (rr0[k] < 0 && rr1[k] < 0) continue;
            float q0[16], q1[16];
            #pragma unroll
            for (int c = 0; c < 16; c++) { q0[c] = 0.f; q1[c] = 0.f; }
            if (rr0[k] >= 0) LOADP(q0, fin, rr0[k]);
            if (rr1[k] >= 0) LOADP(q1, fin, rr1[k]);
            const float* wr = sw + (dz*9 + k)*256;
            #pragma unroll
            for (int ci = 0; ci < 16; ci++) {
                ull v0 = pack2(q0[ci]);
                ull v1 = pack2(q1[ci]);
                const ulonglong2* wp = (const ulonglong2*)(wr + ci*16);
                #pragma unroll
                for (int h = 0; h < 4; h++) {
                    ulonglong2 wv = wp[h];
                    fma2(a0[2*h+0], v0, wv.x); fma2(a0[2*h+1], v0, wv.y);
                    fma2(a1[2*h+0], v1, wv.x); fma2(a1[2*h+1], v1, wv.y);
                }
            }
        }
    }
    float4* fo = (float4*)g_mem + out4;
    STOREP(fo, i0, a0);
    if (has1) { STOREP(fo, i1, a1); }
}

// submanifold k=4 pad=(1,2): 2 sites/thread, 2-phase weight staging (32KB)
__global__ void __launch_bounds__(128) k_conv4(long in4, long out4,
        const float* __restrict__ w, int ioff, int loff, int cidx, int lg) {
    int cnt = g_cnt[cidx];
    if (blockIdx.x*256 >= cnt) return;
    __shared__ __align__(16) float sw[8192];
    int t = blockIdx.x*128 + threadIdx.x;
    int i0 = 2*t, i1 = i0 + 1;
    bool act0 = i0 < cnt, act1 = i1 < cnt;
    int S = 1 << lg, M = (1 << (3*lg)) - 1;
    int site0 = act0 ? g_int[loff + i0] : 0;
    int site1 = act1 ? g_int[loff + i1] : 0;
    int b0 = site0 >> (3*lg), r0 = site0 & M;
    int z0 = r0 >> (2*lg), y0 = (r0 >> lg) & (S-1), x0 = r0 & (S-1);
    int b1 = site1 >> (3*lg), r1 = site1 & M;
    int z1 = r1 >> (2*lg), y1 = (r1 >> lg) & (S-1), x1 = r1 & (S-1);
    const float4* fin = (const float4*)g_mem + in4;
    ull a0[8], a1[8];
    #pragma unroll
    for (int p = 0; p < 8; p++) { a0[p] = 0ull; a1[p] = 0ull; }
    #pragma unroll 1
    for (int ph = 0; ph < 2; ph++) {
        __syncthreads();
        {
            const float4* ws = (const float4*)(w + ph*8192);
            float4* wd = (float4*)sw;
            for (int i = threadIdx.x; i < 2048; i += 128) wd[i] = ws[i];
        }
        __syncthreads();
        #pragma unroll 1
        for (int dzl = 0; dzl < 2; dzl++) {
            int dz = ph*2 + dzl;
            int zz0 = z0 + dz - 1, zz1 = z1 + dz - 1;
            bool zk0 = act0 && ((unsigned)zz0 < (unsigned)S);
            bool zk1 = act1 && ((unsigned)zz1 < (unsigned)S);
            if (!(zk0 | zk1)) continue;
            #pragma unroll 1
            for (int dy = 0; dy < 4; dy++) {
                int yy0 = y0+dy-1, yy1 = y1+dy-1;
                bool yk0 = zk0 && ((unsigned)yy0 < (unsigned)S);
                bool yk1 = zk1 && ((unsigned)yy1 < (unsigned)S);
                if (!(yk0 | yk1)) continue;
                int rr0[4], rr1[4];
                #pragma unroll
                for (int dx = 0; dx < 4; dx++) {
                    int xx0 = x0+dx-1, xx1 = x1+dx-1;
                    rr0[dx] = -1;
                    if (yk0 && (unsigned)xx0 < (unsigned)S)
                        rr0[dx] = g_int[ioff + ((b0 << (3*lg)) + (zz0 << (2*lg)) + (yy0 << lg) + xx0)];
                    rr1[dx] = -1;
                    if (yk1 && (unsigned)xx1 < (unsigned)S)
                        rr1[dx] = g_int[ioff + ((b1 << (3*lg)) + (zz1 << (2*lg)) + (yy1 << lg) + xx1)];
                }
                #pragma unroll
                for (int dx = 0; dx < 4; dx++) {
                    if (rr0[dx] < 0 && rr1[dx] < 0) continue;
                    float q0[16], q1[16];
                    #pragma unroll
                    for (int c = 0; c < 16; c++) { q0[c] = 0.f; q1[c] = 0.f; }
                    if (rr0[dx] >= 0) LOADP(q0, fin, rr0[dx]);
                    if (rr1[dx] >= 0) LOADP(q1, fin, rr1[dx]);
                    const float* wr = sw + ((dzl*4 + dy)*4 + dx)*256;
                    #pragma unroll
                    for (int ci = 0; ci < 16; ci++) {
                        ull v0 = pack2(q0[ci]);
                        ull v1 = pack2(q1[ci]);
                        const ulonglong2* wp = (const ulonglong2*)(wr + ci*16);
                        #pragma unroll
                        for (int h = 0; h < 4; h++) {
                            ulonglong2 wv = wp[h];
                            fma2(a0[2*h+0], v0, wv.x); fma2(a0[2*h+1], v0, wv.y);
                            fma2(a1[2*h+0], v1, wv.x); fma2(a1[2*h+1], v1, wv.y);
                        }
                    }
                }
            }
        }
    }
    float4* fo = (float4*)g_mem + out4;
    if (act0) { STOREP(fo, i0, a0); }
    if (act1) { STOREP(fo, i1, a1); }
}

__global__ void __launch_bounds__(128) k_down(long in4, long out4,
        const float* __restrict__ w, int fioff, int loff, int cidx, int lg) {
    int cnt = g_cnt[cidx];
    if (blockIdx.x*256 >= cnt) return;
    __shared__ __align__(16) float sw[2048];
    {
        const float4* ws = (const float4*)w;
        float4* wd = (float4*)sw;
        for (int i = threadIdx.x; i < 512; i += 128) wd[i] = ws[i];
    }
    __syncthreads();
    int t = blockIdx.x*128 + threadIdx.x;
    int i0 = 2*t, i1 = i0 + 1;
    if (i0 >= cnt) return;
    bool has1 = i1 < cnt;
    int S = 1 << lg, M = (1 << (3*lg)) - 1, flg = lg + 1;
    int site0 = g_int[loff + i0];
    int site1 = has1 ? g_int[loff + i1] : site0;
    int b0 = site0 >> (3*lg), r0 = site0 & M;
    int z0 = r0 >> (2*lg), y0 = (r0 >> lg) & (S-1), x0 = r0 & (S-1);
    int b1 = site1 >> (3*lg), r1 = site1 & M;
    int z1 = r1 >> (2*lg), y1 = (r1 >> lg) & (S-1), x1 = r1 & (S-1);
    const float4* fin = (const float4*)g_mem + in4;
    int rr0[8], rr1[8];
    #pragma unroll
    for (int ta = 0; ta < 2; ta++)
    #pragma unroll
    for (int tb = 0; tb < 2; tb++)
    #pragma unroll
    for (int tc = 0; tc < 2; tc++) {
        int k = (ta*2+tb)*2+tc;
        rr0[k] = g_int[fioff + ((b0 << (3*flg)) + ((2*z0+ta) << (2*flg)) + ((2*y0+tb) << flg) + (2*x0+tc))];
        rr1[k] = has1 ? g_int[fioff + ((b1 << (3*flg)) + ((2*z1+ta) << (2*flg)) + ((2*y1+tb) << flg) + (2*x1+tc))] : -1;
    }
    ull a0[8], a1[8];
    #pragma unroll
    for (int p = 0; p < 8; p++) { a0[p] = 0ull; a1[p] = 0ull; }
    #pragma unroll
    for (int k = 0; k < 8; k++) {
        if (rr0[k] < 0 && rr1[k] < 0) continue;
        float q0[16], q1[16];
        #pragma unroll
        for (int c = 0; c < 16; c++) { q0[c] = 0.f; q1[c] = 0.f; }
        if (rr0[k] >= 0) LOADP(q0, fin, rr0[k]);
        if (rr1[k] >= 0) LOADP(q1, fin, rr1[k]);
        const float* wr = sw + k*256;
        #pragma unroll
        for (int ci = 0; ci < 16; ci++) {
            ull v0 = pack2(q0[ci]);
            ull v1 = pack2(q1[ci]);
            const ulonglong2* wp = (const ulonglong2*)(wr + ci*16);
            #pragma unroll
            for (int h = 0; h < 4; h++) {
                ulonglong2 wv = wp[h];
                fma2(a0[2*h+0], v0, wv.x); fma2(a0[2*h+1], v0, wv.y);
                fma2(a1[2*h+0], v1, wv.x); fma2(a1[2*h+1], v1, wv.y);
            }
        }
    }
    float4* fo = (float4*)g_mem + out4;
    STOREP(fo, i0, a0);
    if (has1) { STOREP(fo, i1, a1); }
}

__global__ void k_up(long in4, long out4, const float* __restrict__ w,
                     int cioff, int loff, int cidx, int lg) {
    int cnt = g_cnt[cidx];
    if (blockIdx.x*256 >= cnt) return;
    __shared__ __align__(16) float sw[2048];
    {
        const float4* ws = (const float4*)w;
        float4* wd = (float4*)sw;
        for (int i = threadIdx.x; i < 512; i += 256) wd[i] = ws[i];
    }
    __syncthreads();
    int i = blockIdx.x*256 + threadIdx.x;
    if (i >= cnt) return;
    int S = 1 << lg, M = (1 << (3*lg)) - 1, lgc = lg - 1;
    int site = g_int[loff + i];
    int b = site >> (3*lg), r = site & M;
    int z = r >> (2*lg), y = (r >> lg) & (S-1), x = r & (S-1);
    int pn = (b << (3*lgc)) + ((z>>1) << (2*lgc)) + ((y>>1) << lgc) + (x>>1);
    int rp = g_int[cioff + pn];
    ull a[8];
    #pragma unroll
    for (int p = 0; p < 8; p++) a[p] = 0ull;
    if (rp >= 0) {
        const float4* fin = (const float4*)g_mem + in4;
        float qf[16];
        LOADP(qf, fin, rp);
        int tap = ((1-(z&1))*2 + (1-(y&1)))*2 + (1-(x&1));
        const float* wr = sw + tap*256;
        FMA16(a, qf, wr);
    }
    float4* fo = (float4*)g_mem + out4;
    STOREP(fo, i, a);
}

__global__ void k_convout(long in4, float* __restrict__ outp,
                          const float* __restrict__ w) {
    __shared__ float sw[432];
    for (int i = threadIdx.x; i < 432; i += 256) sw[i] = w[i];
    __syncthreads();
    int site = blockIdx.x*256 + threadIdx.x;
    const int lg = 6, S = 64;
    if (g_int[IB0 + site] < 0) { outp[site] = 0.f; return; }
    int b = site >> 18, r = site & 0x3ffff;
    int z = r >> 12, y = (r >> 6) & 63, x = r & 63;
    const float4* fin = (const float4*)g_mem + in4;
    float acc = 0.f;
    #pragma unroll 1
    for (int dz = 0; dz < 3; dz++) {
        int zz = z + dz - 1; if ((unsigned)zz >= (unsigned)S) continue;
        int rr[9];
        #pragma unroll
        for (int dy = 0; dy < 3; dy++)
        #pragma unroll
        for (int dx = 0; dx < 3; dx++) {
            int k = dy*3 + dx;
            int yy = y+dy-1, xx = x+dx-1;
            rr[k] = -1;
            if ((unsigned)yy < (unsigned)S && (unsigned)xx < (unsigned)S)
                rr[k] = g_int[IB0 + ((b << (3*lg)) + (zz << (2*lg)) + (yy << lg) + xx)];
        }
        #pragma unroll
        for (int k = 0; k < 9; k++) {
            if (rr[k] < 0) continue;
            float qf[16];
            LOADP(qf, fin, rr[k]);
            const float* wr = sw + (dz*9 + k)*16;
            #pragma unroll
            for (int c = 0; c < 16; c++) acc = fmaf(qf[c], wr[c], acc);
        }
    }
    outp[site] = acc;
}

__global__ void k_hidden(float* __restrict__ outp, long in4) {
    int site = blockIdx.x*256 + threadIdx.x;
    if (site >= NS3) return;
    int rk = g_int[IA3 + site];
    int b = site >> 9, sp = site & 511;
    const float4* f = (const float4*)g_mem + in4;
    #pragma unroll
    for (int h = 0; h < 4; h++) {
        float4 v = (rk >= 0) ? f[h*NS0 + rk] : make_float4(0.f,0.f,0.f,0.f);
        outp[b*8192 + (4*h+0)*512 + sp] = v.x;
        outp[b*8192 + (4*h+1)*512 + sp] = v.y;
        outp[b*8192 + (4*h+2)*512 + sp] = v.z;
        outp[b*8192 + (4*h+3)*512 + sp] = v.w;
    }
}

// ------------------------------- host --------------------------------------

extern "C" void kernel_launch(void* const* d_in, const int* in_sizes, int n_in,
                              void* d_out, int out_size) {
    const float* data      = (const float*)d_in[0];
    const int*   cid       = (const int*)  d_in[1];
    const float* w_prep    = (const float*)d_in[2];
    const float* enc_gamma = (const float*)d_in[3];
    const float* enc_beta  = (const float*)d_in[4];
    const float* enc_wsub  = (const float*)d_in[5];
    const float* enc_wdown = (const float*)d_in[6];
    const float* dec_gamma = (const float*)d_in[7];
    const float* dec_beta  = (const float*)d_in[8];
    const float* dec_wup   = (const float*)d_in[9];
    const float* dec_wsub3 = (const float*)d_in[10];
    const float* dec_wsub4 = (const float*)d_in[11];
    const float* w_out     = (const float*)d_in[12];
    float* outp = (float*)d_out;
    int npts  = in_sizes[0] / 5;
    int mc0   = npts < NS0 ? npts : NS0;
    (void)n_in; (void)out_size;

    k_init<<<1024, 256>>>(NS0/4);
    k_scatter<<<CDIV(npts, 256), 256>>>(data, cid, npts);
    k_emit1<<<NS0/256, 256>>>(0, 0, 6, 0L, 0, IA0, -1, LA0, CA0);

    k_prep<<<CDIV(mc0, 256), 256>>>(BUF_B, w_prep);

    // encoder 0 (64->32)
    k_bnstats<<<GBN, 256>>>(BUF_B, CA0, enc_gamma + 0, enc_beta + 0);
    k_bnapply<<<CDIV(mc0, 256), 256>>>(BUF_B, CA0);
    k_conv3<<<CDIV(mc0, 256), 128>>>(BUF_B, BUF_A, enc_wsub + 0, IA0, LA0, CA0, 6);
    k_emit1<<<NS1/256, 256>>>(1, 1, 5, 0L, IA0, IA1, -1, LA1, CA1);
    k_down<<<CDIV(NS1, 256), 128>>>(BUF_A, BUF_B, enc_wdown + 0, IA0, LA1, CA1, 5);

    // encoder 1 (32->16)
    k_bnstats<<<GBN, 256>>>(BUF_B, CA1, enc_gamma + 16, enc_beta + 16);
    k_bnapply<<<CDIV(NS1, 256), 256>>>(BUF_B, CA1);
    k_conv3<<<CDIV(NS1, 256), 128>>>(BUF_B, BUF_A, enc_wsub + 6912, IA1, LA1, CA1, 5);
    k_emit1<<<NS2/256, 256>>>(2, 1, 4, 0L, IA1, IA2, -1, LA2, CA2);
    k_down<<<CDIV(NS2, 256), 128>>>(BUF_A, BUF_B, enc_wdown + 2048, IA1, LA2, CA2, 4);

    // encoder 2 (16->8)
    k_bnstats<<<GBN, 256>>>(BUF_B, CA2, enc_gamma + 32, enc_beta + 32);
    k_bnapply<<<CDIV(NS2, 256), 256>>>(BUF_B, CA2);
    k_conv3<<<CDIV(NS2, 256), 128>>>(BUF_B, BUF_A, enc_wsub + 13824, IA2, LA2, CA2, 4);
    k_emit1<<<NS3/256, 256>>>(3, 1, 3, 0L, IA2, IA3, -1, LA3, CA3);
    k_down<<<CDIV(NS3, 256), 128>>>(BUF_A, BUF_B, enc_wdown + 4096, IA2, LA3, CA3, 3);

    k_hidden<<<NS3/256, 256>>>(outp, BUF_B);

    // decoder j=0 (8->16)
    k_bnstats<<<GBN, 256>>>(BUF_B, CA3, dec_gamma + 0, dec_beta + 0);
    k_bnapply<<<CDIV(NS3, 256), 256>>>(BUF_B, CA3);
    k_up<<<CDIV(NS2, 256), 256>>>(BUF_B, BUF_A, dec_wup + 0, IA3, LA2, CA2, 4);
    k_conv3<<<CDIV(NS2, 256), 128>>>(BUF_A, BUF_B, dec_wsub3 + 0, IA2, LA2, CA2, 4);
    k_emit1<<<NS2/256, 256>>>(4, 2, 4, BUF_B, IA2, IB2, I2B2, LB2, CB2);
    k_conv4<<<CDIV(NS2, 256), 128>>>(BUF_B, BUF_A, dec_wsub4 + 0, I2B2, LB2, CB2, 4);

    // decoder j=1 (16->32)
    k_bnstats<<<GBN, 256>>>(BUF_A, CB2, dec_gamma + 16, dec_beta + 16);
    k_bnapply<<<CDIV(NS2, 256), 256>>>(BUF_A, CB2);
    k_up<<<CDIV(NS1, 256), 256>>>(BUF_A, BUF_B, dec_wup + 2048, IB2, LA1, CA1, 5);
    k_conv3<<<CDIV(NS1, 256), 128>>>(BUF_B, BUF_A, dec_wsub3 + 6912, IA1, LA1, CA1, 5);
    k_emit1<<<NS1/256, 256>>>(5, 2, 5, BUF_A, IA1, IB1, I2B1, LB1, CB1);
    k_conv4<<<CDIV(NS1, 256), 128>>>(BUF_A, BUF_B, dec_wsub4 + 16384, I2B1, LB1, CB1, 5);

    // decoder j=2 (32->64)
    k_bnstats<<<GBN, 256>>>(BUF_B, CB1, dec_gamma + 32, dec_beta + 32);
    k_bnapply<<<CDIV(NS1, 256), 256>>>(BUF_B, CB1);
    k_up<<<CDIV(mc0, 256), 256>>>(BUF_B, BUF_A, dec_wup + 4096, IB1, LA0, CA0, 6);
    k_conv3<<<CDIV(mc0, 256), 128>>>(BUF_A, BUF_B, dec_wsub3 + 13824, IA0, LA0, CA0, 6);
    k_emit1<<<NS0/256, 256>>>(6, 2, 6, BUF_B, IA0, IB0, I2B0, LB0, CB0);
    k_conv4<<<CDIV(mc0, 256), 128>>>(BUF_B, BUF_A, dec_wsub4 + 32768, I2B0, LB0, CB0, 6);

    k_convout<<<NS0/256, 256>>>(BUF_A, outp + 16*NS3, w_out);
}

// round 17
// speedup vs baseline: 1.1033x; 1.1033x over previous
#include <cuda_runtime.h>
#include <math.h>

#define CDIV(a,b) (((a)+(b)-1)/(b))
#define NS0 (4*64*64*64)
#define NS1 (4*32*32*32)
#define NS2 (4*16*16*16)
#define NS3 (4*8*8*8)
#define GBN 128

__device__ __align__(16) float g_mem[2*16*NS0];
#define BUF_A 0L
#define BUF_B ((long)4*NS0)

#define IA0 0
#define IA1 (IA0+NS0)
#define IA2 (IA1+NS1)
#define IA3 (IA2+NS2)
#define IB0 (IA3+NS3)
#define IB1 (IB0+NS0)
#define IB2 (IB1+NS1)
#define LA0 (IB2+NS2)
#define LA1 (LA0+NS0)
#define LA2 (LA1+NS1)
#define LA3 (LA2+NS2)
#define LB0 (LA3+NS3)
#define LB1 (LB0+NS0)
#define LB2 (LB1+NS1)
#define I2B0 (LB2+NS2)
#define I2B1 (I2B0+NS0)
#define I2B2 (I2B1+NS1)
#define ITOT (I2B2+NS2)
__device__ int g_int[ITOT];

#define CA0 0
#define CA1 1
#define CA2 2
#define CA3 3
#define CB2 4
#define CB1 5
#define CB0 6
__device__ int    g_cnt[8];
__device__ volatile unsigned g_desc[7*4096];
__device__ double g_psum[16*GBN];
__device__ double g_psq [16*GBN];
__device__ float  g_A[16];
__device__ float  g_Bb[16];
__device__ int    g_ticket;

typedef unsigned long long ull;

__device__ __forceinline__ ull pack2(float v) {
    ull r; asm("mov.b64 %0, {%1, %1};" : "=l"(r) : "f"(v)); return r;
}
__device__ __forceinline__ void fma2(ull& a, ull v, ull w) {
    asm("fma.rn.f32x2 %0, %1, %2, %0;" : "+l"(a) : "l"(v), "l"(w));
}
__device__ __forceinline__ float2 unpack2(ull a) {
    float2 f; asm("mov.b64 {%0, %1}, %2;" : "=f"(f.x), "=f"(f.y) : "l"(a)); return f;
}

#define LOADP(dst, f4, r) do { float4 _v; \
    _v=(f4)[(r)];          dst[0]=_v.x; dst[1]=_v.y; dst[2]=_v.z; dst[3]=_v.w; \
    _v=(f4)[NS0+(r)];      dst[4]=_v.x; dst[5]=_v.y; dst[6]=_v.z; dst[7]=_v.w; \
    _v=(f4)[2*NS0+(r)];    dst[8]=_v.x; dst[9]=_v.y; dst[10]=_v.z; dst[11]=_v.w; \
    _v=(f4)[3*NS0+(r)];    dst[12]=_v.x; dst[13]=_v.y; dst[14]=_v.z; dst[15]=_v.w; } while(0)

#define STOREP(f4, r, a) do { float2 _f; float4 _q; \
    _f=unpack2(a[0]); _q.x=_f.x; _q.y=_f.y; _f=unpack2(a[1]); _q.z=_f.x; _q.w=_f.y; (f4)[(r)]=_q; \
    _f=unpack2(a[2]); _q.x=_f.x; _q.y=_f.y; _f=unpack2(a[3]); _q.z=_f.x; _q.w=_f.y; (f4)[NS0+(r)]=_q; \
    _f=unpack2(a[4]); _q.x=_f.x; _q.y=_f.y; _f=unpack2(a[5]); _q.z=_f.x; _q.w=_f.y; (f4)[2*NS0+(r)]=_q; \
    _f=unpack2(a[6]); _q.x=_f.x; _q.y=_f.y; _f=unpack2(a[7]); _q.z=_f.x; _q.w=_f.y; (f4)[3*NS0+(r)]=_q; } while(0)

#define FMA16(acc, q, wr) do { \
    _Pragma("unroll") \
    for (int _ci = 0; _ci < 16; _ci++) { \
        ull _v = pack2(q[_ci]); \
        const ulonglong2* _wp = (const ulonglong2*)((wr) + _ci*16); \
        _Pragma("unroll") \
        for (int _h = 0; _h < 4; _h++) { \
            ulonglong2 _wv = _wp[_h]; \
            fma2(acc[2*_h+0], _v, _wv.x); \
            fma2(acc[2*_h+1], _v, _wv.y); \
        } \
    } } while(0)

// --------------------------- input -----------------------------------------

__global__ void k_init(int n4) {
    float4* p = (float4*)g_mem;
    float4 z = make_float4(0.f,0.f,0.f,0.f);
    for (int i = blockIdx.x*blockDim.x + threadIdx.x; i < n4; i += gridDim.x*blockDim.x)
        p[i] = z;
    for (int i = blockIdx.x*blockDim.x + threadIdx.x; i < 7*4096; i += gridDim.x*blockDim.x)
        g_desc[i] = 0u;
    if (blockIdx.x == 0 && threadIdx.x == 0) g_ticket = 0;
}

__global__ void k_scatter(const float* __restrict__ data, const int* __restrict__ cid, int n) {
    int i = blockIdx.x*blockDim.x + threadIdx.x;
    if (i >= n) return;
    int z = (int)data[i*5+0];
    int y = (int)data[i*5+1];
    int x = (int)data[i*5+2];
    int b = cid[i];
    atomicAdd(&g_mem[((((long)b*64 + z)*64 + y)*64 + x)], 1.0f);
}

// ----- single-pass compaction: publish aggregate, parallel spin-prefix -----

__device__ __forceinline__ bool is_active(int mode, int i, int lg, long foff, int ioff) {
    if (mode == 0) return g_mem[foff + i] > 0.f;
    if (mode == 1) {
        int S = 1 << lg;
        int b = i >> (3*lg), r = i & ((1<<(3*lg))-1);
        int z = r >> (2*lg), y = (r >> lg) & (S-1), x = r & (S-1);
        int flg = lg + 1;
        #pragma unroll
        for (int a = 0; a < 2; a++)
        #pragma unroll
        for (int bb = 0; bb < 2; bb++)
        #pragma unroll
        for (int c = 0; c < 2; c++) {
            int nb = (b << (3*flg)) + ((2*z+a) << (2*flg)) + ((2*y+bb) << flg) + (2*x+c);
            if (g_int[ioff + nb] >= 0) return true;
        }
        return false;
    }
    int r = g_int[ioff + i];
    if (r < 0) return false;
    return ((const float4*)g_mem + foff)[r].x > 0.f;
}

__global__ void k_emit1(int inv, int mode, int lg, long foff, int ioff,
                        int idxout, int idxout2, int listout, int cidx) {
    int t = threadIdx.x, b = blockIdx.x;
    int i = b*256 + t;
    bool a = is_active(mode, i, lg, foff, ioff);
    unsigned bal = __ballot_sync(0xffffffffu, a);
    __shared__ int ws[8];
    __shared__ int sh[8];
    __shared__ int sbase;
    int lane = t & 31, wid = t >> 5;
    if (lane == 0) ws[wid] = __popc(bal);
    __syncthreads();
    int agg = 0;
    #pragma unroll
    for (int j = 0; j < 8; j++) agg += ws[j];
    volatile unsigned* d = g_desc + inv*4096;
    if (t == 0) d[b] = 0x80000000u | (unsigned)agg;
    int pre = 0;
    for (int j = t; j < b; j += 256) {
        unsigned v;
        do { v = d[j]; } while (!(v & 0x80000000u));
        pre += (int)(v & 0x7FFFFFFFu);
    }
    #pragma unroll
    for (int o = 16; o > 0; o >>= 1) pre += __shfl_down_sync(0xffffffffu, pre, o);
    if (lane == 0) sh[wid] = pre;
    __syncthreads();
    if (t == 0) {
        int s = 0;
        #pragma unroll
        for (int j = 0; j < 8; j++) s += sh[j];
        sbase = s;
        if (b == gridDim.x - 1) g_cnt[cidx] = s + agg;
    }
    __syncthreads();
    int base = sbase;
    int woff = 0;
    #pragma unroll
    for (int j = 0; j < 8; j++) if (j < wid) woff += ws[j];
    int pos = base + woff + __popc(bal & ((1u << lane) - 1u));
    g_int[idxout + i] = a ? pos : -1;
    if (idxout2 >= 0)
        g_int[idxout2 + i] = a ? g_int[ioff + i] : -1;
    if (a) g_int[listout + pos] = i;
}

// ------------------------------- BatchNorm ---------------------------------

__global__ void k_bnstats(long in4, int cidx, const float* __restrict__ gamma,
                          const float* __restrict__ beta) {
    int cnt = g_cnt[cidx];
    const float4* f = (const float4*)g_mem + in4;
    float s[16], q[16];
    #pragma unroll
    for (int c = 0; c < 16; c++) { s[c] = 0.f; q[c] = 0.f; }
    for (int i = blockIdx.x*256 + threadIdx.x; i < cnt; i += GBN*256) {
        #pragma unroll
        for (int h = 0; h < 4; h++) {
            float4 v = f[h*NS0 + i];
            s[4*h+0] += v.x; q[4*h+0] += v.x*v.x;
            s[4*h+1] += v.y; q[4*h+1] += v.y*v.y;
            s[4*h+2] += v.z; q[4*h+2] += v.z*v.z;
            s[4*h+3] += v.w; q[4*h+3] += v.w*v.w;
        }
    }
    int lane = threadIdx.x & 31, wid = threadIdx.x >> 5;
    __shared__ float shs[8][16], shq[8][16];
    #pragma unroll
    for (int c = 0; c < 16; c++) {
        float a = s[c], b = q[c];
        #pragma unroll
        for (int o = 16; o > 0; o >>= 1) {
            a += __shfl_down_sync(0xffffffffu, a, o);
            b += __shfl_down_sync(0xffffffffu, b, o);
        }
        if (lane == 0) { shs[wid][c] = a; shq[wid][c] = b; }
    }
    __syncthreads();
    if (threadIdx.x < 16) {
        double A = 0.0, Bq = 0.0;
        #pragma unroll
        for (int j = 0; j < 8; j++) { A += (double)shs[j][threadIdx.x]; Bq += (double)shq[j][threadIdx.x]; }
        g_psum[threadIdx.x*GBN + blockIdx.x] = A;
        g_psq [threadIdx.x*GBN + blockIdx.x] = Bq;
    }
    __threadfence();
    __shared__ int lastf;
    if (threadIdx.x == 0) {
        int o = atomicAdd(&g_ticket, 1);
        lastf = (o == GBN - 1) ? 1 : 0;
    }
    __syncthreads();
    if (lastf) {
        __threadfence();
        if (threadIdx.x < 16) {
            int c = threadIdx.x;
            volatile double* vs = g_psum;
            volatile double* vq = g_psq;
            double S = 0.0, Q = 0.0;
            for (int g = 0; g < GBN; g++) { S += vs[c*GBN + g]; Q += vq[c*GBN + g]; }
            double n = (double)cnt; if (n < 1.0) n = 1.0;
            double mean = S / n;
            double var  = Q / n - mean*mean;
            double inv  = 1.0 / sqrt(var + 1e-4);
            double Af   = (double)gamma[c] * inv;
            g_A[c]  = (float)Af;
            g_Bb[c] = (float)((double)beta[c] - mean*Af);
        }
        if (threadIdx.x == 0) g_ticket = 0;
    }
}

__global__ void k_bnapply(long in4, int cidx) {
    int cnt = g_cnt[cidx];
    int i = blockIdx.x*256 + threadIdx.x;
    if (i >= cnt) return;
    float4* f = (float4*)g_mem + in4;
    #pragma unroll
    for (int h = 0; h < 4; h++) {
        float4 v = f[h*NS0 + i];
        v.x = fmaf(v.x, g_A[4*h+0], g_Bb[4*h+0]); v.x = v.x > 0.f ? v.x : 0.f;
        v.y = fmaf(v.y, g_A[4*h+1], g_Bb[4*h+1]); v.y = v.y > 0.f ? v.y : 0.f;
        v.z = fmaf(v.z, g_A[4*h+2], g_Bb[4*h+2]); v.z = v.z > 0.f ? v.z : 0.f;
        v.w = fmaf(v.w, g_A[4*h+3], g_Bb[4*h+3]); v.w = v.w > 0.f ? v.w : 0.f;
        f[h*NS0 + i] = v;
    }
}

// ------------------------------ convolutions -------------------------------

__global__ void k_prep(long out4, const float* __restrict__ w) {
    int cnt = g_cnt[CA0];
    if (blockIdx.x*256 >= cnt) return;
    __shared__ __align__(16) float sw[432];
    for (int i = threadIdx.x; i < 432; i += 256) sw[i] = w[i];
    __syncthreads();
    int i = blockIdx.x*256 + threadIdx.x;
    if (i >= cnt) return;
    int site = g_int[LA0 + i];
    const int lg = 6, S = 64;
    int b = site >> 18, r = site & 0x3ffff;
    int z = r >> 12, y = (r >> 6) & 63, x = r & 63;
    ull a[8];
    #pragma unroll
    for (int p = 0; p < 8; p++) a[p] = 0ull;
    #pragma unroll 1
    for (int dz = 0; dz < 3; dz++) {
        int zz = z + dz - 1; if ((unsigned)zz >= (unsigned)S) continue;
        #pragma unroll 1
        for (int dy = 0; dy < 3; dy++) {
            int yy = y + dy - 1; if ((unsigned)yy >= (unsigned)S) continue;
            #pragma unroll
            for (int dx = 0; dx < 3; dx++) {
                int xx = x + dx - 1; if ((unsigned)xx >= (unsigned)S) continue;
                float v = g_mem[(b << (3*lg)) + (zz << (2*lg)) + (yy << lg) + xx];
                if (v == 0.f) continue;
                ull vv = pack2(v);
                const ulonglong2* wp = (const ulonglong2*)(sw + ((dz*3+dy)*3+dx)*16);
                #pragma unroll
                for (int h = 0; h < 4; h++) {
                    ulonglong2 wv = wp[h];
                    fma2(a[2*h+0], vv, wv.x);
                    fma2(a[2*h+1], vv, wv.y);
                }
            }
        }
    }
    float4* fo = (float4*)g_mem + out4;
    STOREP(fo, i, a);
}

// submanifold k=3: 2 sites/thread, batched rank prefetch, per-tap skip
__global__ void __launch_bounds__(128) k_conv3(long in4, long out4,
        const float* __restrict__ w, int ioff, int loff, int cidx, int lg) {
    int cnt = g_cnt[cidx];
    if (blockIdx.x*256 >= cnt) return;
    __shared__ __align__(16) float sw[6912];
    {
        const float4* ws = (const float4*)w;
        float4* wd = (float4*)sw;
        for (int i = threadIdx.x; i < 1728; i += 128) wd[i] = ws[i];
    }
    __syncthreads();
    int t = blockIdx.x*128 + threadIdx.x;
    int i0 = 2*t, i1 = i0 + 1;
    if (i0 >= cnt) return;
    bool has1 = i1 < cnt;
    int S = 1 << lg, M = (1 << (3*lg)) - 1;
    int site0 = g_int[loff + i0];
    int site1 = has1 ? g_int[loff + i1] : site0;
    int b0 = site0 >> (3*lg), r0 = site0 & M;
    int z0 = r0 >> (2*lg), y0 = (r0 >> lg) & (S-1), x0 = r0 & (S-1);
    int b1 = site1 >> (3*lg), r1 = site1 & M;
    int z1 = r1 >> (2*lg), y1 = (r1 >> lg) & (S-1), x1 = r1 & (S-1);
    const float4* fin = (const float4*)g_mem + in4;
    ull a0[8], a1[8];
    #pragma unroll
    for (int p = 0; p < 8; p++) { a0[p] = 0ull; a1[p] = 0ull; }
    #pragma unroll 1
    for (int dz = 0; dz < 3; dz++) {
        int zz0 = z0 + dz - 1, zz1 = z1 + dz - 1;
        bool zk0 = (unsigned)zz0 < (unsigned)S;
        bool zk1 = has1 && ((unsigned)zz1 < (unsigned)S);
        int rr0[9], rr1[9];
        #pragma unroll
        for (int dy = 0; dy < 3; dy++)
        #pragma unroll
        for (int dx = 0; dx < 3; dx++) {
            int k = dy*3 + dx;
            int yy0 = y0+dy-1, xx0 = x0+dx-1;
            rr0[k] = -1;
            if (zk0 && (unsigned)yy0 < (unsigned)S && (unsigned)xx0 < (unsigned)S)
                rr0[k] = g_int[ioff + ((b0 << (3*lg)) + (zz0 << (2*lg)) + (yy0 << lg) + xx0)];
            int yy1 = y1+dy-1, xx1 = x1+dx-1;
            rr1[k] = -1;
            if (zk1 && (unsigned)yy1 < (unsigned)S && (unsigned)xx1 < (unsigned)S)
                rr1[k] = g_int[ioff + ((b1 << (3*lg)) + (zz1 << (2*lg)) + (yy1 << lg) + xx1)];
        }
        #pragma unroll
        for (int k = 0; k < 9; k++) {
            if (rr0[k] < 0 && rr1[k] < 0) continue;
            float q0[16], q1[16];
            #pragma unroll
            for (int c = 0; c < 16; c++) { q0[c] = 0.f; q1[c] = 0.f; }
            if (rr0[k] >= 0) LOADP(q0, fin, rr0[k]);
            if (rr1[k] >= 0) LOADP(q1, fin, rr1[k]);
            const float* wr = sw + (dz*9 + k)*256;
            #pragma unroll
            for (int ci = 0; ci < 16; ci++) {
                ull v0 = pack2(q0[ci]);
                ull v1 = pack2(q1[ci]);
                const ulonglong2* wp = (const ulonglong2*)(wr + ci*16);
                #pragma unroll
                for (int h = 0; h < 4; h++) {
                    ulonglong2 wv = wp[h];
                    fma2(a0[2*h+0], v0, wv.x); fma2(a0[2*h+1], v0, wv.y);
                    fma2(a1[2*h+0], v1, wv.x); fma2(a1[2*h+1], v1, wv.y);
                }
            }
        }
    }
    float4* fo = (float4*)g_mem + out4;
    STOREP(fo, i0, a0);
    if (has1) { STOREP(fo, i1, a1); }
}

// submanifold k=4 pad=(1,2): 2 sites/thread, dz-sliced weights, data-rank map
__global__ void __launch_bounds__(128) k_conv4(long in4, long out4,
        const float* __restrict__ w, int ioff, int loff, int cidx, int lg) {
    int cnt = g_cnt[cidx];
    if (blockIdx.x*256 >= cnt) return;
    __shared__ __align__(16) float sw[4096];
    int t = blockIdx.x*128 + threadIdx.x;
    int i0 = 2*t, i1 = i0 + 1;
    bool act0 = i0 < cnt, act1 = i1 < cnt;
    int S = 1 << lg, M = (1 << (3*lg)) - 1;
    int site0 = act0 ? g_int[loff + i0] : 0;
    int site1 = act1 ? g_int[loff + i1] : 0;
    int b0 = site0 >> (3*lg), r0 = site0 & M;
    int z0 = r0 >> (2*lg), y0 = (r0 >> lg) & (S-1), x0 = r0 & (S-1);
    int b1 = site1 >> (3*lg), r1 = site1 & M;
    int z1 = r1 >> (2*lg), y1 = (r1 >> lg) & (S-1), x1 = r1 & (S-1);
    const float4* fin = (const float4*)g_mem + in4;
    ull a0[8], a1[8];
    #pragma unroll
    for (int p = 0; p < 8; p++) { a0[p] = 0ull; a1[p] = 0ull; }
    #pragma unroll 1
    for (int dz = 0; dz < 4; dz++) {
        __syncthreads();
        {
            const float4* ws = (const float4*)(w + dz*4096);
            float4* wd = (float4*)sw;
            for (int i = threadIdx.x; i < 1024; i += 128) wd[i] = ws[i];
        }
        __syncthreads();
        int zz0 = z0 + dz - 1, zz1 = z1 + dz - 1;
        bool zk0 = act0 && ((unsigned)zz0 < (unsigned)S);
        bool zk1 = act1 && ((unsigned)zz1 < (unsigned)S);
        if (!(zk0 | zk1)) continue;
        #pragma unroll 1
        for (int dy = 0; dy < 4; dy++) {
            int yy0 = y0+dy-1, yy1 = y1+dy-1;
            bool yk0 = zk0 && ((unsigned)yy0 < (unsigned)S);
            bool yk1 = zk1 && ((unsigned)yy1 < (unsigned)S);
            if (!(yk0 | yk1)) continue;
            int rr0[4], rr1[4];
            #pragma unroll
            for (int dx = 0; dx < 4; dx++) {
                int xx0 = x0+dx-1, xx1 = x1+dx-1;
                rr0[dx] = -1;
                if (yk0 && (unsigned)xx0 < (unsigned)S)
                    rr0[dx] = g_int[ioff + ((b0 << (3*lg)) + (zz0 << (2*lg)) + (yy0 << lg) + xx0)];
                rr1[dx] = -1;
                if (yk1 && (unsigned)xx1 < (unsigned)S)
                    rr1[dx] = g_int[ioff + ((b1 << (3*lg)) + (zz1 << (2*lg)) + (yy1 << lg) + xx1)];
            }
            #pragma unroll
            for (int dx = 0; dx < 4; dx++) {
                if (rr0[dx] < 0 && rr1[dx] < 0) continue;
                float q0[16], q1[16];
                #pragma unroll
                for (int c = 0; c < 16; c++) { q0[c] = 0.f; q1[c] = 0.f; }
                if (rr0[dx] >= 0) LOADP(q0, fin, rr0[dx]);
                if (rr1[dx] >= 0) LOADP(q1, fin, rr1[dx]);
                const float* wr = sw + (dy*4 + dx)*256;
                #pragma unroll
                for (int ci = 0; ci < 16; ci++) {
                    ull v0 = pack2(q0[ci]);
                    ull v1 = pack2(q1[ci]);
                    const ulonglong2* wp = (const ulonglong2*)(wr + ci*16);
                    #pragma unroll
                    for (int h = 0; h < 4; h++) {
                        ulonglong2 wv = wp[h];
                        fma2(a0[2*h+0], v0, wv.x); fma2(a0[2*h+1], v0, wv.y);
                        fma2(a1[2*h+0], v1, wv.x); fma2(a1[2*h+1], v1, wv.y);
                    }
                }
            }
        }
    }
    float4* fo = (float4*)g_mem + out4;
    if (act0) { STOREP(fo, i0, a0); }
    if (act1) { STOREP(fo, i1, a1); }
}

__global__ void __launch_bounds__(128) k_down(long in4, long out4,
        const float* __restrict__ w, int fioff, int loff, int cidx, int lg) {
    int cnt = g_cnt[cidx];
    if (blockIdx.x*256 >= cnt) return;
    __shared__ __align__(16) float sw[2048];
    {
        const float4* ws = (const float4*)w;
        float4* wd = (float4*)sw;
        for (int i = threadIdx.x; i < 512; i += 128) wd[i] = ws[i];
    }
    __syncthreads();
    int t = blockIdx.x*128 + threadIdx.x;
    int i0 = 2*t, i1 = i0 + 1;
    if (i0 >= cnt) return;
    bool has1 = i1 < cnt;
    int S = 1 << lg, M = (1 << (3*lg)) - 1, flg = lg + 1;
    int site0 = g_int[loff + i0];
    int site1 = has1 ? g_int[loff + i1] : site0;
    int b0 = site0 >> (3*lg), r0 = site0 & M;
    int z0 = r0 >> (2*lg), y0 = (r0 >> lg) & (S-1), x0 = r0 & (S-1);
    int b1 = site1 >> (3*lg), r1 = site1 & M;
    int z1 = r1 >> (2*lg), y1 = (r1 >> lg) & (S-1), x1 = r1 & (S-1);
    const float4* fin = (const float4*)g_mem + in4;
    int rr0[8], rr1[8];
    #pragma unroll
    for (int ta = 0; ta < 2; ta++)
    #pragma unroll
    for (int tb = 0; tb < 2; tb++)
    #pragma unroll
    for (int tc = 0; tc < 2; tc++) {
        int k = (ta*2+tb)*2+tc;
        rr0[k] = g_int[fioff + ((b0 << (3*flg)) + ((2*z0+ta) << (2*flg)) + ((2*y0+tb) << flg) + (2*x0+tc))];
        rr1[k] = has1 ? g_int[fioff + ((b1 << (3*flg)) + ((2*z1+ta) << (2*flg)) + ((2*y1+tb) << flg) + (2*x1+tc))] : -1;
    }
    ull a0[8], a1[8];
    #pragma unroll
    for (int p = 0; p < 8; p++) { a0[p] = 0ull; a1[p] = 0ull; }
    #pragma unroll
    for (int k = 0; k < 8; k++) {
        if (rr0[k] < 0 && rr1[k] < 0) continue;
        float q0[16], q1[16];
        #pragma unroll
        for (int c = 0; c < 16; c++) { q0[c] = 0.f; q1[c] = 0.f; }
        if (rr0[k] >= 0) LOADP(q0, fin, rr0[k]);
        if (rr1[k] >= 0) LOADP(q1, fin, rr1[k]);
        const float* wr = sw + k*256;
        #pragma unroll
        for (int ci = 0; ci < 16; ci++) {
            ull v0 = pack2(q0[ci]);
            ull v1 = pack2(q1[ci]);
            const ulonglong2* wp = (const ulonglong2*)(wr + ci*16);
            #pragma unroll
            for (int h = 0; h < 4; h++) {
                ulonglong2 wv = wp[h];
                fma2(a0[2*h+0], v0, wv.x); fma2(a0[2*h+1], v0, wv.y);
                fma2(a1[2*h+0], v1, wv.x); fma2(a1[2*h+1], v1, wv.y);
            }
        }
    }
    float4* fo = (float4*)g_mem + out4;
    STOREP(fo, i0, a0);
    if (has1) { STOREP(fo, i1, a1); }
}

__global__ void k_up(long in4, long out4, const float* __restrict__ w,
                     int cioff, int loff, int cidx, int lg) {
    int cnt = g_cnt[cidx];
    if (blockIdx.x*256 >= cnt) return;
    __shared__ __align__(16) float sw[2048];
    {
        const float4* ws = (const float4*)w;
        float4* wd = (float4*)sw;
        for (int i = threadIdx.x; i < 512; i += 256) wd[i] = ws[i];
    }
    __syncthreads();
    int i = blockIdx.x*256 + threadIdx.x;
    if (i >= cnt) return;
    int S = 1 << lg, M = (1 << (3*lg)) - 1, lgc = lg - 1;
    int site = g_int[loff + i];
    int b = site >> (3*lg), r = site & M;
    int z = r >> (2*lg), y = (r >> lg) & (S-1), x = r & (S-1);
    int pn = (b << (3*lgc)) + ((z>>1) << (2*lgc)) + ((y>>1) << lgc) + (x>>1);
    int rp = g_int[cioff + pn];
    ull a[8];
    #pragma unroll
    for (int p = 0; p < 8; p++) a[p] = 0ull;
    if (rp >= 0) {
        const float4* fin = (const float4*)g_mem + in4;
        float qf[16];
        LOADP(qf, fin, rp);
        int tap = ((1-(z&1))*2 + (1-(y&1)))*2 + (1-(x&1));
        const float* wr = sw + tap*256;
        FMA16(a, qf, wr);
    }
    float4* fo = (float4*)g_mem + out4;
    STOREP(fo, i, a);
}

__global__ void k_convout(long in4, float* __restrict__ outp,
                          const float* __restrict__ w) {
    __shared__ float sw[432];
    for (int i = threadIdx.x; i < 432; i += 256) sw[i] = w[i];
    __syncthreads();
    int site = blockIdx.x*256 + threadIdx.x;
    const int lg = 6, S = 64;
    if (g_int[IB0 + site] < 0) { outp[site] = 0.f; return; }
    int b = site >> 18, r = site & 0x3ffff;
    int z = r >> 12, y = (r >> 6) & 63, x = r & 63;
    const float4* fin = (const float4*)g_mem + in4;
    float acc = 0.f;
    #pragma unroll 1
    for (int dz = 0; dz < 3; dz++) {
        int zz = z + dz - 1; if ((unsigned)zz >= (unsigned)S) continue;
        int rr[9];
        #pragma unroll
        for (int dy = 0; dy < 3; dy++)
        #pragma unroll
        for (int dx = 0; dx < 3; dx++) {
            int k = dy*3 + dx;
            int yy = y+dy-1, xx = x+dx-1;
            rr[k] = -1;
            if ((unsigned)yy < (unsigned)S && (unsigned)xx < (unsigned)S)
                rr[k] = g_int[IB0 + ((b << (3*lg)) + (zz << (2*lg)) + (yy << lg) + xx)];
        }
        #pragma unroll
        for (int k = 0; k < 9; k++) {
            if (rr[k] < 0) continue;
            float qf[16];
            LOADP(qf, fin, rr[k]);
            const float* wr = sw + (dz*9 + k)*16;
            #pragma unroll
            for (int c = 0; c < 16; c++) acc = fmaf(qf[c], wr[c], acc);
        }
    }
    outp[site] = acc;
}

__global__ void k_hidden(float* __restrict__ outp, long in4) {
    int site = blockIdx.x*256 + threadIdx.x;
    if (site >= NS3) return;
    int rk = g_int[IA3 + site];
    int b = site >> 9, sp = site & 511;
    const float4* f = (const float4*)g_mem + in4;
    #pragma unroll
    for (int h = 0; h < 4; h++) {
        float4 v = (rk >= 0) ? f[h*NS0 + rk] : make_float4(0.f,0.f,0.f,0.f);
        outp[b*8192 + (4*h+0)*512 + sp] = v.x;
        outp[b*8192 + (4*h+1)*512 + sp] = v.y;
        outp[b*8192 + (4*h+2)*512 + sp] = v.z;
        outp[b*8192 + (4*h+3)*512 + sp] = v.w;
    }
}

// ------------------------------- host --------------------------------------

extern "C" void kernel_launch(void* const* d_in, const int* in_sizes, int n_in,
                              void* d_out, int out_size) {
    const float* data      = (const float*)d_in[0];
    const int*   cid       = (const int*)  d_in[1];
    const float* w_prep    = (const float*)d_in[2];
    const float* enc_gamma = (const float*)d_in[3];
    const float* enc_beta  = (const float*)d_in[4];
    const float* enc_wsub  = (const float*)d_in[5];
    const float* enc_wdown = (const float*)d_in[6];
    const float* dec_gamma = (const float*)d_in[7];
    const float* dec_beta  = (const float*)d_in[8];
    const float* dec_wup   = (const float*)d_in[9];
    const float* dec_wsub3 = (const float*)d_in[10];
    const float* dec_wsub4 = (const float*)d_in[11];
    const float* w_out     = (const float*)d_in[12];
    float* outp = (float*)d_out;
    int npts  = in_sizes[0] / 5;
    int mc0   = npts < NS0 ? npts : NS0;
    (void)n_in; (void)out_size;

    k_init<<<1024, 256>>>(NS0/4);
    k_scatter<<<CDIV(npts, 256), 256>>>(data, cid, npts);
    k_emit1<<<NS0/256, 256>>>(0, 0, 6, 0L, 0, IA0, -1, LA0, CA0);

    k_prep<<<CDIV(mc0, 256), 256>>>(BUF_B, w_prep);

    // encoder 0 (64->32)
    k_bnstats<<<GBN, 256>>>(BUF_B, CA0, enc_gamma + 0, enc_beta + 0);
    k_bnapply<<<CDIV(mc0, 256), 256>>>(BUF_B, CA0);
    k_conv3<<<CDIV(mc0, 256), 128>>>(BUF_B, BUF_A, enc_wsub + 0, IA0, LA0, CA0, 6);
    k_emit1<<<NS1/256, 256>>>(1, 1, 5, 0L, IA0, IA1, -1, LA1, CA1);
    k_down<<<CDIV(NS1, 256), 128>>>(BUF_A, BUF_B, enc_wdown + 0, IA0, LA1, CA1, 5);

    // encoder 1 (32->16)
    k_bnstats<<<GBN, 256>>>(BUF_B, CA1, enc_gamma + 16, enc_beta + 16);
    k_bnapply<<<CDIV(NS1, 256), 256>>>(BUF_B, CA1);
    k_conv3<<<CDIV(NS1, 256), 128>>>(BUF_B, BUF_A, enc_wsub + 6912, IA1, LA1, CA1, 5);
    k_emit1<<<NS2/256, 256>>>(2, 1, 4, 0L, IA1, IA2, -1, LA2, CA2);
    k_down<<<CDIV(NS2, 256), 128>>>(BUF_A, BUF_B, enc_wdown + 2048, IA1, LA2, CA2, 4);

    // encoder 2 (16->8)
    k_bnstats<<<GBN, 256>>>(BUF_B, CA2, enc_gamma + 32, enc_beta + 32);
    k_bnapply<<<CDIV(NS2, 256), 256>>>(BUF_B, CA2);
    k_conv3<<<CDIV(NS2, 256), 128>>>(BUF_B, BUF_A, enc_wsub + 13824, IA2, LA2, CA2, 4);
    k_emit1<<<NS3/256, 256>>>(3, 1, 3, 0L, IA2, IA3, -1, LA3, CA3);
    k_down<<<CDIV(NS3, 256), 128>>>(BUF_A, BUF_B, enc_wdown + 4096, IA2, LA3, CA3, 3);

    k_hidden<<<NS3/256, 256>>>(outp, BUF_B);

    // decoder j=0 (8->16)
    k_bnstats<<<GBN, 256>>>(BUF_B, CA3, dec_gamma + 0, dec_beta + 0);
    k_bnapply<<<CDIV(NS3, 256), 256>>>(BUF_B, CA3);
    k_up<<<CDIV(NS2, 256), 256>>>(BUF_B, BUF_A, dec_wup + 0, IA3, LA2, CA2, 4);
    k_conv3<<<CDIV(NS2, 256), 128>>>(BUF_A, BUF_B, dec_wsub3 + 0, IA2, LA2, CA2, 4);
    k_emit1<<<NS2/256, 256>>>(4, 2, 4, BUF_B, IA2, IB2, I2B2, LB2, CB2);
    k_conv4<<<CDIV(NS2, 256), 128>>>(BUF_B, BUF_A, dec_wsub4 + 0, I2B2, LB2, CB2, 4);

    // decoder j=1 (16->32)
    k_bnstats<<<GBN, 256>>>(BUF_A, CB2, dec_gamma + 16, dec_beta + 16);
    k_bnapply<<<CDIV(NS2, 256), 256>>>(BUF_A, CB2);
    k_up<<<CDIV(NS1, 256), 256>>>(BUF_A, BUF_B, dec_wup + 2048, IB2, LA1, CA1, 5);
    k_conv3<<<CDIV(NS1, 256), 128>>>(BUF_B, BUF_A, dec_wsub3 + 6912, IA1, LA1, CA1, 5);
    k_emit1<<<NS1/256, 256>>>(5, 2, 5, BUF_A, IA1, IB1, I2B1, LB1, CB1);
    k_conv4<<<CDIV(NS1, 256), 128>>>(BUF_A, BUF_B, dec_wsub4 + 16384, I2B1, LB1, CB1, 5);

    // decoder j=2 (32->64)
    k_bnstats<<<GBN, 256>>>(BUF_B, CB1, dec_gamma + 32, dec_beta + 32);
    k_bnapply<<<CDIV(NS1, 256), 256>>>(BUF_B, CB1);
    k_up<<<CDIV(mc0, 256), 256>>>(BUF_B, BUF_A, dec_wup + 4096, IB1, LA0, CA0, 6);
    k_conv3<<<CDIV(mc0, 256), 128>>>(BUF_A, BUF_B, dec_wsub3 + 13824, IA0, LA0, CA0, 6);
    k_emit1<<<NS0/256, 256>>>(6, 2, 6, BUF_B, IA0, IB0, I2B0, LB0, CB0);
    k_conv4<<<CDIV(mc0, 256), 128>>>(BUF_B, BUF_A, dec_wsub4 + 32768, I2B0, LB0, CB0, 6);

    k_convout<<<NS0/256, 256>>>(BUF_A, outp + 16*NS3, w_out);
}